// round 1
// baseline (speedup 1.0000x reference)
#include <cuda_runtime.h>
#include <math.h>

#define NODE_DIM_   128
#define NUM_IRREPS_ 224
#define SPH_DIM_    480
#define HIDDEN_     576
#define NUM_BASIS_  20
#define N_NODES_    30000
#define N_EDGES_    480000

// Scratch (device globals: allowed; no runtime allocation)
__device__ float g_hidden[(size_t)N_NODES_ * NODE_DIM_];        // 15.4 MB
__device__ float g_scalar_out[(size_t)N_NODES_ * HIDDEN_];      // 69.1 MB

// ---------------------------------------------------------------------------
// init: out_scalar = x_scalar ; out_sph = x_spherical  (vectorized copy)
// ---------------------------------------------------------------------------
__global__ void init_out_kernel(const float4* __restrict__ x_scalar,
                                const float4* __restrict__ x_sph,
                                float4* __restrict__ out) {
    const int NS4 = N_NODES_ * NODE_DIM_ / 4;
    const int NT4 = (N_NODES_ * NODE_DIM_ + N_NODES_ * SPH_DIM_) / 4;
    int i = blockIdx.x * blockDim.x + threadIdx.x;
    if (i < NS4)        out[i] = x_scalar[i];
    else if (i < NT4)   out[i] = x_sph[i - NS4];
}

// ---------------------------------------------------------------------------
// Classic 64x64x16 register-tiled SGEMM with bias (+ optional SiLU epilogue)
// C[M,N] = act(A[M,K] @ B[K,N] + bias)   (N multiple of 64, K multiple of 16)
// ---------------------------------------------------------------------------
template <bool DO_SILU>
__global__ __launch_bounds__(256) void sgemm_bias(
    const float* __restrict__ A, const float* __restrict__ B,
    const float* __restrict__ bias, float* __restrict__ C,
    int M, int N, int K) {
    __shared__ float As[16][65];   // padded: conflict-free transposed store
    __shared__ float Bs[16][64];
    const int bm = blockIdx.y * 64;
    const int bn = blockIdx.x * 64;
    const int tid = threadIdx.x;
    const int tx = tid & 15;
    const int ty = tid >> 4;

    float acc[4][4] = {};

    for (int k0 = 0; k0 < K; k0 += 16) {
        #pragma unroll
        for (int i = 0; i < 4; i++) {
            int idx = tid + 256 * i;          // 0..1023
            int m = idx >> 4, k = idx & 15;   // consecutive tid -> consecutive k
            int gm = bm + m;
            As[k][m] = (gm < M) ? A[(size_t)gm * K + k0 + k] : 0.0f;
        }
        #pragma unroll
        for (int i = 0; i < 4; i++) {
            int idx = tid + 256 * i;
            int k = idx >> 6, n = idx & 63;   // consecutive tid -> consecutive n
            Bs[k][n] = B[(size_t)(k0 + k) * N + bn + n];
        }
        __syncthreads();
        #pragma unroll
        for (int k = 0; k < 16; k++) {
            float a[4], b[4];
            #pragma unroll
            for (int i = 0; i < 4; i++) a[i] = As[k][ty + 16 * i];
            #pragma unroll
            for (int j = 0; j < 4; j++) b[j] = Bs[k][tx + 16 * j];
            #pragma unroll
            for (int i = 0; i < 4; i++)
                #pragma unroll
                for (int j = 0; j < 4; j++)
                    acc[i][j] = fmaf(a[i], b[j], acc[i][j]);
        }
        __syncthreads();
    }

    #pragma unroll
    for (int i = 0; i < 4; i++) {
        int m = bm + ty + 16 * i;
        if (m >= M) continue;
        #pragma unroll
        for (int j = 0; j < 4; j++) {
            int n = bn + tx + 16 * j;
            float v = acc[i][j] + bias[n];
            if (DO_SILU) v = v / (1.0f + expf(-v));   // silu = v * sigmoid(v)
            C[(size_t)m * N + n] = v;
        }
    }
}

// ---------------------------------------------------------------------------
// Fused edge kernel:
//   fw   = (rbf @ Wrbf + brbf) * fcut
//   fo   = scalar_out[src] * fw
//   scatter-add msg_scalar (fo[448:576]) into out_scalar[dst]
//   msg_sph = x_sph[src]*gate_state[idx] + rsh*gate_edge[idx]; scatter to dst
// 192 threads; thread t owns Wrbf columns {t, t+192, t+384} in registers.
// ---------------------------------------------------------------------------
__device__ __forceinline__ int irrep_of(int k) {
    if (k < 128) return k;
    if (k < 320) return 128 + (k - 128) / 3;
    return 192 + (k - 320) / 5;
}

__global__ __launch_bounds__(192) void edge_kernel(
    const float* __restrict__ rbf, const float* __restrict__ fcut,
    const float* __restrict__ rsh, const int* __restrict__ edge_index,
    const float* __restrict__ Wrbf, const float* __restrict__ brbf,
    const float* __restrict__ x_sph,
    float* __restrict__ out_scalar, float* __restrict__ out_sph) {
    const float* __restrict__ scalar_out = g_scalar_out;

    __shared__ float rbf_s[NUM_BASIS_];
    __shared__ float gate_s[2 * NUM_IRREPS_];   // 448: gate_state | gate_edge
    __shared__ int src_sh, dst_sh;
    __shared__ float fcut_sh;

    const int t = threadIdx.x;

    // Preload this thread's 3 Wrbf columns + bias into registers (reused forever)
    float w0[NUM_BASIS_], w1[NUM_BASIS_], w2[NUM_BASIS_];
    #pragma unroll
    for (int k = 0; k < NUM_BASIS_; k++) {
        w0[k] = Wrbf[k * HIDDEN_ + t];
        w1[k] = Wrbf[k * HIDDEN_ + t + 192];
        w2[k] = Wrbf[k * HIDDEN_ + t + 384];
    }
    const float bb0 = brbf[t], bb1 = brbf[t + 192], bb2 = brbf[t + 384];

    // Spherical element indices this thread handles and their irreps
    const int k_a = t, k_b = t + 192, k_c = t + 384;   // k_c valid iff t < 96
    const int ir_a = irrep_of(k_a);
    const int ir_b = irrep_of(k_b);
    const int ir_c = (t < 96) ? irrep_of(k_c) : 0;

    for (int e = blockIdx.x; e < N_EDGES_; e += gridDim.x) {
        if (t < NUM_BASIS_) rbf_s[t] = rbf[e * NUM_BASIS_ + t];
        if (t == 32) dst_sh = edge_index[e];               // edge_index[0]
        if (t == 33) src_sh = edge_index[N_EDGES_ + e];    // edge_index[1]
        if (t == 34) fcut_sh = fcut[e];
        __syncthreads();

        const int src = src_sh;
        const int dst = dst_sh;
        const float fc = fcut_sh;

        float rb[NUM_BASIS_];
        #pragma unroll
        for (int k = 0; k < NUM_BASIS_; k++) rb[k] = rbf_s[k];

        float a0 = bb0, a1 = bb1, a2 = bb2;
        #pragma unroll
        for (int k = 0; k < NUM_BASIS_; k++) {
            a0 = fmaf(rb[k], w0[k], a0);
            a1 = fmaf(rb[k], w1[k], a1);
            a2 = fmaf(rb[k], w2[k], a2);
        }
        const float* __restrict__ so = scalar_out + (size_t)src * HIDDEN_;
        const float fo0 = so[t]       * (a0 * fc);
        const float fo1 = so[t + 192] * (a1 * fc);
        const float fo2 = so[t + 384] * (a2 * fc);

        gate_s[t]       = fo0;           // cols [0,192)
        gate_s[t + 192] = fo1;           // cols [192,384)
        if (t < 64) gate_s[t + 384] = fo2;   // cols [384,448)
        __syncthreads();

        // message_scalar = fo[:, 448:576]  (cols t+384 for t>=64 -> out col t-64)
        if (t >= 64) atomicAdd(&out_scalar[(size_t)dst * NODE_DIM_ + (t - 64)], fo2);

        // message_spherical
        const float* __restrict__ xs = x_sph + (size_t)src * SPH_DIM_;
        const float* __restrict__ rs = rsh + (size_t)e * SPH_DIM_;
        float* __restrict__ os = out_sph + (size_t)dst * SPH_DIM_;

        float m_a = xs[k_a] * gate_s[ir_a] + rs[k_a] * gate_s[NUM_IRREPS_ + ir_a];
        atomicAdd(&os[k_a], m_a);
        float m_b = xs[k_b] * gate_s[ir_b] + rs[k_b] * gate_s[NUM_IRREPS_ + ir_b];
        atomicAdd(&os[k_b], m_b);
        if (t < 96) {
            float m_c = xs[k_c] * gate_s[ir_c] + rs[k_c] * gate_s[NUM_IRREPS_ + ir_c];
            atomicAdd(&os[k_c], m_c);
        }
        __syncthreads();   // protect gate_s / rbf_s before next iteration
    }
}

// ---------------------------------------------------------------------------
extern "C" void kernel_launch(void* const* d_in, const int* in_sizes, int n_in,
                              void* d_out, int out_size) {
    const float* x_scalar = (const float*)d_in[0];
    const float* x_sph    = (const float*)d_in[1];
    const float* rbf      = (const float*)d_in[2];
    const float* fcut     = (const float*)d_in[3];
    const float* rsh      = (const float*)d_in[4];
    const int*   eidx     = (const int*)d_in[5];
    const float* W1       = (const float*)d_in[6];
    const float* b1       = (const float*)d_in[7];
    const float* W2       = (const float*)d_in[8];
    const float* b2       = (const float*)d_in[9];
    const float* Wrbf     = (const float*)d_in[10];
    const float* brbf     = (const float*)d_in[11];

    float* out        = (float*)d_out;
    float* out_scalar = out;
    float* out_sph    = out + (size_t)N_NODES_ * NODE_DIM_;

    float* hidden = nullptr;
    float* so     = nullptr;
    cudaGetSymbolAddress((void**)&hidden, g_hidden);
    cudaGetSymbolAddress((void**)&so, g_scalar_out);

    // 1) initialize output with residual (x_scalar | x_spherical)
    {
        int total4 = (N_NODES_ * NODE_DIM_ + N_NODES_ * SPH_DIM_) / 4;
        int blocks = (total4 + 255) / 256;
        init_out_kernel<<<blocks, 256>>>((const float4*)x_scalar,
                                         (const float4*)x_sph,
                                         (float4*)out);
    }

    // 2) hidden = silu(x_scalar @ W1 + b1)      [30000,128]
    {
        dim3 grid(NODE_DIM_ / 64, (N_NODES_ + 63) / 64);
        sgemm_bias<true><<<grid, 256>>>(x_scalar, W1, b1, hidden,
                                        N_NODES_, NODE_DIM_, NODE_DIM_);
    }

    // 3) scalar_out = hidden @ W2 + b2          [30000,576]
    {
        dim3 grid(HIDDEN_ / 64, (N_NODES_ + 63) / 64);
        sgemm_bias<false><<<grid, 256>>>(hidden, W2, b2, so,
                                         N_NODES_, HIDDEN_, NODE_DIM_);
    }

    // 4) fused edge filter + gating + scatter
    edge_kernel<<<1776, 192>>>(rbf, fcut, rsh, eidx, Wrbf, brbf,
                               x_sph, out_scalar, out_sph);
}

// round 3
// speedup vs baseline: 1.0785x; 1.0785x over previous
#include <cuda_runtime.h>
#include <cstdint>
#include <math.h>

#define NODE_DIM_   128
#define NUM_IRREPS_ 224
#define SPH_DIM_    480
#define HIDDEN_     576
#define NUM_BASIS_  20
#define N_NODES_    30000
#define N_EDGES_    480000
#define EPB_        4                      // edges per block phase
#define NGROUPS_    (N_EDGES_ / EPB_)      // 120000
#define NBUF_       3                      // message slots in flight

// Scratch (device globals: allowed; no runtime allocation)
__device__ float g_hidden[(size_t)N_NODES_ * NODE_DIM_];        // 15.4 MB
__device__ float g_scalar_out[(size_t)N_NODES_ * HIDDEN_];      // 69.1 MB

// ---------------------------------------------------------------------------
// init: out = [x_scalar | x_spherical]  (residual), vectorized copy
// ---------------------------------------------------------------------------
__global__ void init_out_kernel(const float4* __restrict__ x_scalar,
                                const float4* __restrict__ x_sph,
                                float4* __restrict__ out) {
    const int NS4 = N_NODES_ * NODE_DIM_ / 4;
    const int NT4 = (N_NODES_ * NODE_DIM_ + N_NODES_ * SPH_DIM_) / 4;
    int i = blockIdx.x * blockDim.x + threadIdx.x;
    if (i < NS4)        out[i] = x_scalar[i];
    else if (i < NT4)   out[i] = x_sph[i - NS4];
}

// ---------------------------------------------------------------------------
// Classic 64x64x16 register-tiled SGEMM with bias (+ optional SiLU epilogue)
// ---------------------------------------------------------------------------
template <bool DO_SILU>
__global__ __launch_bounds__(256) void sgemm_bias(
    const float* __restrict__ A, const float* __restrict__ B,
    const float* __restrict__ bias, float* __restrict__ C,
    int M, int N, int K) {
    __shared__ float As[16][65];
    __shared__ float Bs[16][64];
    const int bm = blockIdx.y * 64;
    const int bn = blockIdx.x * 64;
    const int tid = threadIdx.x;
    const int tx = tid & 15;
    const int ty = tid >> 4;

    float acc[4][4] = {};

    for (int k0 = 0; k0 < K; k0 += 16) {
        #pragma unroll
        for (int i = 0; i < 4; i++) {
            int idx = tid + 256 * i;
            int m = idx >> 4, k = idx & 15;
            int gm = bm + m;
            As[k][m] = (gm < M) ? A[(size_t)gm * K + k0 + k] : 0.0f;
        }
        #pragma unroll
        for (int i = 0; i < 4; i++) {
            int idx = tid + 256 * i;
            int k = idx >> 6, n = idx & 63;
            Bs[k][n] = B[(size_t)(k0 + k) * N + bn + n];
        }
        __syncthreads();
        #pragma unroll
        for (int k = 0; k < 16; k++) {
            float a[4], b[4];
            #pragma unroll
            for (int i = 0; i < 4; i++) a[i] = As[k][ty + 16 * i];
            #pragma unroll
            for (int j = 0; j < 4; j++) b[j] = Bs[k][tx + 16 * j];
            #pragma unroll
            for (int i = 0; i < 4; i++)
                #pragma unroll
                for (int j = 0; j < 4; j++)
                    acc[i][j] = fmaf(a[i], b[j], acc[i][j]);
        }
        __syncthreads();
    }

    #pragma unroll
    for (int i = 0; i < 4; i++) {
        int m = bm + ty + 16 * i;
        if (m >= M) continue;
        #pragma unroll
        for (int j = 0; j < 4; j++) {
            int n = bn + tx + 16 * j;
            float v = acc[i][j] + bias[n];
            if (DO_SILU) v = v / (1.0f + expf(-v));
            C[(size_t)m * N + n] = v;
        }
    }
}

// ---------------------------------------------------------------------------
// Fused edge kernel, batched 4 edges per phase, TMA bulk reduce-add scatter.
// ---------------------------------------------------------------------------
__device__ __forceinline__ int irrep_of(int k) {
    if (k < 128) return k;
    if (k < 320) return 128 + (k - 128) / 3;
    return 192 + (k - 320) / 5;
}

__global__ __launch_bounds__(192, 2) void edge_kernel(
    const float* __restrict__ rbf, const float* __restrict__ fcut,
    const float* __restrict__ rsh, const int* __restrict__ edge_index,
    const float* __restrict__ Wrbf, const float* __restrict__ brbf,
    const float* __restrict__ x_sph,
    float* __restrict__ out_scalar, float* __restrict__ out_sph) {
    const float* __restrict__ scalar_out = g_scalar_out;

    __shared__ float rbf_s[EPB_][NUM_BASIS_];
    __shared__ int   dst_s[EPB_];
    __shared__ int   src_s[EPB_];
    __shared__ float fcut_s[EPB_];
    __shared__ float gate_s[EPB_][2 * NUM_IRREPS_];             // per-edge 448 gates
    __shared__ __align__(16) float msg_s[NBUF_][EPB_][SPH_DIM_ + NODE_DIM_]; // 608 ea

    const int t = threadIdx.x;

    // this thread's 3 filter columns: weights + bias in registers, reused forever
    float w0[NUM_BASIS_], w1[NUM_BASIS_], w2[NUM_BASIS_];
    #pragma unroll
    for (int k = 0; k < NUM_BASIS_; k++) {
        w0[k] = Wrbf[k * HIDDEN_ + t];
        w1[k] = Wrbf[k * HIDDEN_ + t + 192];
        w2[k] = Wrbf[k * HIDDEN_ + t + 384];
    }
    const float bb0 = brbf[t], bb1 = brbf[t + 192], bb2 = brbf[t + 384];

    const int k_a = t, k_b = t + 192, k_c = t + 384;   // k_c valid iff t < 96
    const int ir_a = irrep_of(k_a);
    const int ir_b = irrep_of(k_b);
    const int ir_c = (t < 96) ? irrep_of(k_c) : 0;

    int slot = 0;
    for (int g = blockIdx.x; g < NGROUPS_; g += gridDim.x) {
        const int e0 = g * EPB_;

        // throttle: slot may still be read by an in-flight bulk reduce
        if (t == 0) asm volatile("cp.async.bulk.wait_group.read 2;" ::: "memory");

        // metadata loads
        if (t < EPB_ * NUM_BASIS_) {
            int e = t / NUM_BASIS_, k = t % NUM_BASIS_;
            rbf_s[e][k] = rbf[(size_t)(e0 + e) * NUM_BASIS_ + k];
        } else if (t < 84) {
            dst_s[t - 80] = edge_index[e0 + (t - 80)];
        } else if (t < 88) {
            src_s[t - 84] = edge_index[N_EDGES_ + e0 + (t - 84)];
        } else if (t < 92) {
            fcut_s[t - 88] = fcut[e0 + (t - 88)];
        }
        __syncthreads();

        // ---- Phase B: filter GEMM + gather + gating, 4 edges at once ----
        float a0[EPB_], a1[EPB_], a2[EPB_];
        #pragma unroll
        for (int e = 0; e < EPB_; e++) { a0[e] = bb0; a1[e] = bb1; a2[e] = bb2; }
        #pragma unroll
        for (int k = 0; k < NUM_BASIS_; k++) {
            #pragma unroll
            for (int e = 0; e < EPB_; e++) {
                float r = rbf_s[e][k];
                a0[e] = fmaf(r, w0[k], a0[e]);
                a1[e] = fmaf(r, w1[k], a1[e]);
                a2[e] = fmaf(r, w2[k], a2[e]);
            }
        }
        // independent gathers (MLP = 12)
        float s0[EPB_], s1[EPB_], s2[EPB_];
        #pragma unroll
        for (int e = 0; e < EPB_; e++) {
            const float* __restrict__ so = scalar_out + (size_t)src_s[e] * HIDDEN_;
            s0[e] = so[t];
            s1[e] = so[t + 192];
            s2[e] = so[t + 384];
        }
        #pragma unroll
        for (int e = 0; e < EPB_; e++) {
            const float fc = fcut_s[e];
            float fo0 = s0[e] * (a0[e] * fc);
            float fo1 = s1[e] * (a1[e] * fc);
            float fo2 = s2[e] * (a2[e] * fc);
            gate_s[e][t]       = fo0;                 // cols [0,192)
            gate_s[e][t + 192] = fo1;                 // cols [192,384)
            if (t < 64) gate_s[e][t + 384] = fo2;     // cols [384,448)
            else        msg_s[slot][e][SPH_DIM_ + (t - 64)] = fo2;  // message_scalar
        }
        __syncthreads();

        // ---- Phase C: spherical messages into staging buffer ----
        #pragma unroll
        for (int e = 0; e < EPB_; e++) {
            const float* __restrict__ xs = x_sph + (size_t)src_s[e] * SPH_DIM_;
            const float* __restrict__ rs = rsh + (size_t)(e0 + e) * SPH_DIM_;
            float ga = gate_s[e][ir_a], gae = gate_s[e][NUM_IRREPS_ + ir_a];
            float gb = gate_s[e][ir_b], gbe = gate_s[e][NUM_IRREPS_ + ir_b];
            msg_s[slot][e][k_a] = xs[k_a] * ga + rs[k_a] * gae;
            msg_s[slot][e][k_b] = xs[k_b] * gb + rs[k_b] * gbe;
            if (t < 96) {
                float gc = gate_s[e][ir_c], gce = gate_s[e][NUM_IRREPS_ + ir_c];
                msg_s[slot][e][k_c] = xs[k_c] * gc + rs[k_c] * gce;
            }
        }
        __syncthreads();

        // ---- Drain: bulk reduce-add into out[dst] (replaces 608 atomics/edge)
        if (t == 0) {
            asm volatile("fence.proxy.async.shared::cta;" ::: "memory");
            #pragma unroll
            for (int e = 0; e < EPB_; e++) {
                const int d = dst_s[e];
                unsigned int src_sph, src_sc;
                asm("{ .reg .u64 a; cvta.to.shared.u64 a, %1; cvt.u32.u64 %0, a; }"
                    : "=r"(src_sph) : "l"(&msg_s[slot][e][0]));
                asm("{ .reg .u64 a; cvta.to.shared.u64 a, %1; cvt.u32.u64 %0, a; }"
                    : "=r"(src_sc) : "l"(&msg_s[slot][e][SPH_DIM_]));
                asm volatile(
                    "cp.reduce.async.bulk.global.shared::cta.bulk_group.add.f32 [%0], [%1], %2;"
                    :: "l"(out_sph + (size_t)d * SPH_DIM_), "r"(src_sph),
                       "n"(SPH_DIM_ * 4) : "memory");
                asm volatile(
                    "cp.reduce.async.bulk.global.shared::cta.bulk_group.add.f32 [%0], [%1], %2;"
                    :: "l"(out_scalar + (size_t)d * NODE_DIM_), "r"(src_sc),
                       "n"(NODE_DIM_ * 4) : "memory");
            }
            asm volatile("cp.async.bulk.commit_group;" ::: "memory");
        }
        slot = (slot + 1 == NBUF_) ? 0 : slot + 1;
    }
    // ensure all reduces fully complete before kernel exit
    if (t == 0) asm volatile("cp.async.bulk.wait_group 0;" ::: "memory");
}

// ---------------------------------------------------------------------------
extern "C" void kernel_launch(void* const* d_in, const int* in_sizes, int n_in,
                              void* d_out, int out_size) {
    const float* x_scalar = (const float*)d_in[0];
    const float* x_sph    = (const float*)d_in[1];
    const float* rbf      = (const float*)d_in[2];
    const float* fcut     = (const float*)d_in[3];
    const float* rsh      = (const float*)d_in[4];
    const int*   eidx     = (const int*)d_in[5];
    const float* W1       = (const float*)d_in[6];
    const float* b1       = (const float*)d_in[7];
    const float* W2       = (const float*)d_in[8];
    const float* b2       = (const float*)d_in[9];
    const float* Wrbf     = (const float*)d_in[10];
    const float* brbf     = (const float*)d_in[11];

    float* out        = (float*)d_out;
    float* out_scalar = out;
    float* out_sph    = out + (size_t)N_NODES_ * NODE_DIM_;

    float* hidden = nullptr;
    float* so     = nullptr;
    cudaGetSymbolAddress((void**)&hidden, g_hidden);
    cudaGetSymbolAddress((void**)&so, g_scalar_out);

    // 1) residual init
    {
        int total4 = (N_NODES_ * NODE_DIM_ + N_NODES_ * SPH_DIM_) / 4;
        int blocks = (total4 + 255) / 256;
        init_out_kernel<<<blocks, 256>>>((const float4*)x_scalar,
                                         (const float4*)x_sph,
                                         (float4*)out);
    }
    // 2) hidden = silu(x_scalar @ W1 + b1)
    {
        dim3 grid(NODE_DIM_ / 64, (N_NODES_ + 63) / 64);
        sgemm_bias<true><<<grid, 256>>>(x_scalar, W1, b1, hidden,
                                        N_NODES_, NODE_DIM_, NODE_DIM_);
    }
    // 3) scalar_out = hidden @ W2 + b2
    {
        dim3 grid(HIDDEN_ / 64, (N_NODES_ + 63) / 64);
        sgemm_bias<false><<<grid, 256>>>(hidden, W2, b2, so,
                                         N_NODES_, HIDDEN_, NODE_DIM_);
    }
    // 4) fused edge filter + gating + bulk-reduce scatter
    edge_kernel<<<592, 192>>>(rbf, fcut, rsh, eidx, Wrbf, brbf,
                              x_sph, out_scalar, out_sph);
}

// round 4
// speedup vs baseline: 1.3149x; 1.2192x over previous
#include <cuda_runtime.h>
#include <cstdint>
#include <math.h>

#define NODE_DIM_   128
#define NUM_IRREPS_ 224
#define SPH_DIM_    480
#define HIDDEN_     576
#define NUM_BASIS_  20
#define N_NODES_    30000
#define N_EDGES_    480000
#define EPB_        4
#define SCAN_BLKS_  118          // ceil(30000/256)

// Scratch (device globals)
__device__ float g_hidden[(size_t)N_NODES_ * NODE_DIM_];
__device__ float g_scalar_out[(size_t)N_NODES_ * HIDDEN_];
__device__ int   g_count[N_NODES_];
__device__ int   g_offs[N_NODES_];
__device__ int   g_cursor[N_NODES_];
__device__ int   g_part[128];
__device__ int   g_perm[N_EDGES_];

// ---------------------------------------------------------------------------
__global__ void init_out_kernel(const float4* __restrict__ x_scalar,
                                const float4* __restrict__ x_sph,
                                float4* __restrict__ out) {
    const int NS4 = N_NODES_ * NODE_DIM_ / 4;
    const int NT4 = (N_NODES_ * NODE_DIM_ + N_NODES_ * SPH_DIM_) / 4;
    int i = blockIdx.x * blockDim.x + threadIdx.x;
    if (i < NS4)        out[i] = x_scalar[i];
    else if (i < NT4)   out[i] = x_sph[i - NS4];
}

// ---------------- counting sort by dst ----------------
__global__ void zero_counts() {
    int i = blockIdx.x * blockDim.x + threadIdx.x;
    if (i < N_NODES_) g_count[i] = 0;
}
__global__ void hist_kernel(const int* __restrict__ edge_index) {
    int e = blockIdx.x * blockDim.x + threadIdx.x;
    if (e < N_EDGES_) atomicAdd(&g_count[edge_index[e]], 1);   // dst = row 0
}
__global__ void scan1_kernel() {
    __shared__ int s[256];
    int tid = threadIdx.x;
    int i = blockIdx.x * 256 + tid;
    int v = (i < N_NODES_) ? g_count[i] : 0;
    s[tid] = v; __syncthreads();
    #pragma unroll
    for (int d = 1; d < 256; d <<= 1) {
        int x = (tid >= d) ? s[tid - d] : 0;
        __syncthreads();
        s[tid] += x;
        __syncthreads();
    }
    if (i < N_NODES_) g_offs[i] = s[tid] - v;          // exclusive
    if (tid == 255) g_part[blockIdx.x] = s[255];
}
__global__ void scan2_kernel() {
    __shared__ int s[128];
    int tid = threadIdx.x;
    int v = (tid < SCAN_BLKS_) ? g_part[tid] : 0;
    s[tid] = v; __syncthreads();
    #pragma unroll
    for (int d = 1; d < 128; d <<= 1) {
        int x = (tid >= d) ? s[tid - d] : 0;
        __syncthreads();
        s[tid] += x;
        __syncthreads();
    }
    if (tid < SCAN_BLKS_) g_part[tid] = s[tid] - v;    // exclusive
}
__global__ void scan3_kernel() {
    int i = blockIdx.x * 256 + threadIdx.x;
    if (i < N_NODES_) {
        int o = g_offs[i] + g_part[blockIdx.x];
        g_offs[i] = o;
        g_cursor[i] = o;
    }
}
__global__ void perm_kernel(const int* __restrict__ edge_index) {
    int e = blockIdx.x * blockDim.x + threadIdx.x;
    if (e < N_EDGES_) {
        int d = edge_index[e];
        int p = atomicAdd(&g_cursor[d], 1);
        g_perm[p] = e;
    }
}

// ---------------------------------------------------------------------------
// SGEMM (unchanged)
// ---------------------------------------------------------------------------
template <bool DO_SILU>
__global__ __launch_bounds__(256) void sgemm_bias(
    const float* __restrict__ A, const float* __restrict__ B,
    const float* __restrict__ bias, float* __restrict__ C,
    int M, int N, int K) {
    __shared__ float As[16][65];
    __shared__ float Bs[16][64];
    const int bm = blockIdx.y * 64;
    const int bn = blockIdx.x * 64;
    const int tid = threadIdx.x;
    const int tx = tid & 15;
    const int ty = tid >> 4;
    float acc[4][4] = {};
    for (int k0 = 0; k0 < K; k0 += 16) {
        #pragma unroll
        for (int i = 0; i < 4; i++) {
            int idx = tid + 256 * i;
            int m = idx >> 4, k = idx & 15;
            int gm = bm + m;
            As[k][m] = (gm < M) ? A[(size_t)gm * K + k0 + k] : 0.0f;
        }
        #pragma unroll
        for (int i = 0; i < 4; i++) {
            int idx = tid + 256 * i;
            int k = idx >> 6, n = idx & 63;
            Bs[k][n] = B[(size_t)(k0 + k) * N + bn + n];
        }
        __syncthreads();
        #pragma unroll
        for (int k = 0; k < 16; k++) {
            float a[4], b[4];
            #pragma unroll
            for (int i = 0; i < 4; i++) a[i] = As[k][ty + 16 * i];
            #pragma unroll
            for (int j = 0; j < 4; j++) b[j] = Bs[k][tx + 16 * j];
            #pragma unroll
            for (int i = 0; i < 4; i++)
                #pragma unroll
                for (int j = 0; j < 4; j++)
                    acc[i][j] = fmaf(a[i], b[j], acc[i][j]);
        }
        __syncthreads();
    }
    #pragma unroll
    for (int i = 0; i < 4; i++) {
        int m = bm + ty + 16 * i;
        if (m >= M) continue;
        #pragma unroll
        for (int j = 0; j < 4; j++) {
            int n = bn + tx + 16 * j;
            float v = acc[i][j] + bias[n];
            if (DO_SILU) v = v / (1.0f + expf(-v));
            C[(size_t)m * N + n] = v;
        }
    }
}

// ---------------------------------------------------------------------------
// Node-parallel fused kernel: block owns node n (= dst), iterates its CSR
// edge list in batches of 4; accumulates messages in registers; writes once.
// 576 threads: thread t owns filter column t.
// ---------------------------------------------------------------------------
__device__ __forceinline__ int irrep_of(int k) {
    if (k < 128) return k;
    if (k < 320) return 128 + (k - 128) / 3;
    return 192 + (k - 320) / 5;
}

__global__ __launch_bounds__(576, 2) void node_kernel(
    const float* __restrict__ rbf, const float* __restrict__ fcut,
    const float* __restrict__ rsh, const int* __restrict__ edge_index,
    const float* __restrict__ Wrbf, const float* __restrict__ brbf,
    const float* __restrict__ x_sph,
    float* __restrict__ out_scalar, float* __restrict__ out_sph) {
    const float* __restrict__ scalar_out = g_scalar_out;

    __shared__ float rbf_s[EPB_][NUM_BASIS_];
    __shared__ int   src_s[EPB_];
    __shared__ int   eid_s[EPB_];
    __shared__ float fcut_s[EPB_];
    __shared__ float gate_s[EPB_][2 * NUM_IRREPS_];

    const int t = threadIdx.x;

    // thread-owned filter column t
    float w[NUM_BASIS_];
    #pragma unroll
    for (int k = 0; k < NUM_BASIS_; k++) w[k] = Wrbf[k * HIDDEN_ + t];
    const float bb = brbf[t];
    const int ir = (t < SPH_DIM_) ? irrep_of(t) : 0;

    for (int n = blockIdx.x; n < N_NODES_; n += gridDim.x) {
        const int off = g_offs[n];
        const int deg = g_count[n];
        if (deg == 0) continue;                 // uniform per block

        float acc_sph = 0.0f;     // t < 480: spherical element t
        float acc_sc  = 0.0f;     // t >= 448: scalar col t-448

        for (int b = 0; b < deg; b += EPB_) {
            // ---- metadata (redundant perm loads broadcast-coalesce) ----
            if (t < 80) {
                int sl = t / 20, bi = b + sl;
                int eid = g_perm[off + ((bi < deg) ? bi : b)];
                rbf_s[sl][t % 20] = rbf[(size_t)eid * NUM_BASIS_ + (t % 20)];
            } else if (t < 84) {
                int sl = t - 80, bi = b + sl;
                int eid = g_perm[off + ((bi < deg) ? bi : b)];
                src_s[sl] = edge_index[N_EDGES_ + eid];
            } else if (t < 88) {
                int sl = t - 84, bi = b + sl;
                int eid = g_perm[off + ((bi < deg) ? bi : b)];
                fcut_s[sl] = (bi < deg) ? fcut[eid] : 0.0f;
            } else if (t < 92) {
                int sl = t - 88, bi = b + sl;
                eid_s[sl] = g_perm[off + ((bi < deg) ? bi : b)];
            }
            __syncthreads();

            int   srcv[EPB_];
            float fc[EPB_];
            #pragma unroll
            for (int e = 0; e < EPB_; e++) { srcv[e] = src_s[e]; fc[e] = fcut_s[e]; }

            // gathers (coalesced rows), issued before FMA chain
            float s[EPB_];
            #pragma unroll
            for (int e = 0; e < EPB_; e++)
                s[e] = __ldg(&scalar_out[(size_t)srcv[e] * HIDDEN_ + t]);

            float a[EPB_];
            #pragma unroll
            for (int e = 0; e < EPB_; e++) a[e] = bb;
            #pragma unroll
            for (int k = 0; k < NUM_BASIS_; k++) {
                #pragma unroll
                for (int e = 0; e < EPB_; e++)
                    a[e] = fmaf(rbf_s[e][k], w[k], a[e]);
            }

            #pragma unroll
            for (int e = 0; e < EPB_; e++) s[e] = s[e] * (a[e] * fc[e]);  // fo

            if (t < 2 * NUM_IRREPS_) {
                #pragma unroll
                for (int e = 0; e < EPB_; e++) gate_s[e][t] = s[e];
            } else {
                acc_sc += s[0] + s[1] + s[2] + s[3];
            }
            __syncthreads();

            // ---- spherical messages ----
            if (t < SPH_DIM_) {
                float xv[EPB_], rv[EPB_];
                #pragma unroll
                for (int e = 0; e < EPB_; e++) {
                    xv[e] = __ldg(&x_sph[(size_t)srcv[e] * SPH_DIM_ + t]);
                    rv[e] = __ldcs(&rsh[(size_t)eid_s[e] * SPH_DIM_ + t]);
                }
                #pragma unroll
                for (int e = 0; e < EPB_; e++) {
                    acc_sph = fmaf(xv[e], gate_s[e][ir], acc_sph);
                    acc_sph = fmaf(rv[e], gate_s[e][NUM_IRREPS_ + ir], acc_sph);
                }
            }
            __syncthreads();   // gate_s/meta reused next batch
        }

        // ---- single write per node (out already holds residual) ----
        if (t < SPH_DIM_)
            out_sph[(size_t)n * SPH_DIM_ + t] += acc_sph;
        if (t >= 2 * NUM_IRREPS_)
            out_scalar[(size_t)n * NODE_DIM_ + (t - 2 * NUM_IRREPS_)] += acc_sc;
    }
}

// ---------------------------------------------------------------------------
extern "C" void kernel_launch(void* const* d_in, const int* in_sizes, int n_in,
                              void* d_out, int out_size) {
    const float* x_scalar = (const float*)d_in[0];
    const float* x_sph    = (const float*)d_in[1];
    const float* rbf      = (const float*)d_in[2];
    const float* fcut     = (const float*)d_in[3];
    const float* rsh      = (const float*)d_in[4];
    const int*   eidx     = (const int*)d_in[5];
    const float* W1       = (const float*)d_in[6];
    const float* b1       = (const float*)d_in[7];
    const float* W2       = (const float*)d_in[8];
    const float* b2       = (const float*)d_in[9];
    const float* Wrbf     = (const float*)d_in[10];
    const float* brbf     = (const float*)d_in[11];

    float* out        = (float*)d_out;
    float* out_scalar = out;
    float* out_sph    = out + (size_t)N_NODES_ * NODE_DIM_;

    float* hidden = nullptr;
    float* so     = nullptr;
    cudaGetSymbolAddress((void**)&hidden, g_hidden);
    cudaGetSymbolAddress((void**)&so, g_scalar_out);

    // residual init
    {
        int total4 = (N_NODES_ * NODE_DIM_ + N_NODES_ * SPH_DIM_) / 4;
        init_out_kernel<<<(total4 + 255) / 256, 256>>>(
            (const float4*)x_scalar, (const float4*)x_sph, (float4*)out);
    }

    // counting sort by dst (CSR)
    zero_counts<<<SCAN_BLKS_, 256>>>();
    hist_kernel<<<(N_EDGES_ + 255) / 256, 256>>>(eidx);
    scan1_kernel<<<SCAN_BLKS_, 256>>>();
    scan2_kernel<<<1, 128>>>();
    scan3_kernel<<<SCAN_BLKS_, 256>>>();
    perm_kernel<<<(N_EDGES_ + 255) / 256, 256>>>(eidx);

    // node MLP
    {
        dim3 grid(NODE_DIM_ / 64, (N_NODES_ + 63) / 64);
        sgemm_bias<true><<<grid, 256>>>(x_scalar, W1, b1, hidden,
                                        N_NODES_, NODE_DIM_, NODE_DIM_);
    }
    {
        dim3 grid(HIDDEN_ / 64, (N_NODES_ + 63) / 64);
        sgemm_bias<false><<<grid, 256>>>(hidden, W2, b2, so,
                                         N_NODES_, HIDDEN_, NODE_DIM_);
    }

    // fused node-parallel message kernel
    node_kernel<<<296, 576>>>(rbf, fcut, rsh, eidx, Wrbf, brbf,
                              x_sph, out_scalar, out_sph);
}

// round 5
// speedup vs baseline: 1.5090x; 1.1477x over previous
#include <cuda_runtime.h>
#include <cstdint>
#include <math.h>

#define NODE_DIM_   128
#define NUM_IRREPS_ 224
#define SPH_DIM_    480
#define HIDDEN_     576
#define NUM_BASIS_  20
#define N_NODES_    30000
#define N_EDGES_    480000
#define EPB_        8
#define MAXD_       32
#define SCAN_BLKS_  118          // ceil(30000/256)

// Scratch (device globals)
__device__ float g_hidden[(size_t)N_NODES_ * NODE_DIM_];
__device__ float g_scalar_out[(size_t)N_NODES_ * HIDDEN_];
__device__ int   g_count[N_NODES_];
__device__ int   g_offs[N_NODES_];
__device__ int   g_cursor[N_NODES_];
__device__ int   g_part[128];
__device__ int   g_perm[N_EDGES_];

// ---------------------------------------------------------------------------
// init: residual copy into out  +  zero the histogram counters
// ---------------------------------------------------------------------------
__global__ void init_out_kernel(const float4* __restrict__ x_scalar,
                                const float4* __restrict__ x_sph,
                                float4* __restrict__ out) {
    const int NS4 = N_NODES_ * NODE_DIM_ / 4;
    const int NT4 = (N_NODES_ * NODE_DIM_ + N_NODES_ * SPH_DIM_) / 4;
    int i = blockIdx.x * blockDim.x + threadIdx.x;
    if (i < N_NODES_) g_count[i] = 0;
    if (i < NS4)        out[i] = x_scalar[i];
    else if (i < NT4)   out[i] = x_sph[i - NS4];
}

// ---------------- counting sort by dst ----------------
__global__ void hist_kernel(const int* __restrict__ edge_index) {
    int e = blockIdx.x * blockDim.x + threadIdx.x;
    if (e < N_EDGES_) atomicAdd(&g_count[edge_index[e]], 1);   // dst = row 0
}
__global__ void scan1_kernel() {
    __shared__ int s[256];
    int tid = threadIdx.x;
    int i = blockIdx.x * 256 + tid;
    int v = (i < N_NODES_) ? g_count[i] : 0;
    s[tid] = v; __syncthreads();
    #pragma unroll
    for (int d = 1; d < 256; d <<= 1) {
        int x = (tid >= d) ? s[tid - d] : 0;
        __syncthreads();
        s[tid] += x;
        __syncthreads();
    }
    if (i < N_NODES_) g_offs[i] = s[tid] - v;          // exclusive
    if (tid == 255) g_part[blockIdx.x] = s[255];
}
__global__ void scan2_kernel() {
    __shared__ int s[128];
    int tid = threadIdx.x;
    int v = (tid < SCAN_BLKS_) ? g_part[tid] : 0;
    s[tid] = v; __syncthreads();
    #pragma unroll
    for (int d = 1; d < 128; d <<= 1) {
        int x = (tid >= d) ? s[tid - d] : 0;
        __syncthreads();
        s[tid] += x;
        __syncthreads();
    }
    if (tid < SCAN_BLKS_) g_part[tid] = s[tid] - v;    // exclusive
}
__global__ void scan3_kernel() {
    int i = blockIdx.x * 256 + threadIdx.x;
    if (i < N_NODES_) {
        int o = g_offs[i] + g_part[blockIdx.x];
        g_offs[i] = o;
        g_cursor[i] = o;
    }
}
__global__ void perm_kernel(const int* __restrict__ edge_index) {
    int e = blockIdx.x * blockDim.x + threadIdx.x;
    if (e < N_EDGES_) {
        int d = edge_index[e];
        int p = atomicAdd(&g_cursor[d], 1);
        g_perm[p] = e;
    }
}

// ---------------------------------------------------------------------------
// SGEMM (unchanged)
// ---------------------------------------------------------------------------
template <bool DO_SILU>
__global__ __launch_bounds__(256) void sgemm_bias(
    const float* __restrict__ A, const float* __restrict__ B,
    const float* __restrict__ bias, float* __restrict__ C,
    int M, int N, int K) {
    __shared__ float As[16][65];
    __shared__ float Bs[16][64];
    const int bm = blockIdx.y * 64;
    const int bn = blockIdx.x * 64;
    const int tid = threadIdx.x;
    const int tx = tid & 15;
    const int ty = tid >> 4;
    float acc[4][4] = {};
    for (int k0 = 0; k0 < K; k0 += 16) {
        #pragma unroll
        for (int i = 0; i < 4; i++) {
            int idx = tid + 256 * i;
            int m = idx >> 4, k = idx & 15;
            int gm = bm + m;
            As[k][m] = (gm < M) ? A[(size_t)gm * K + k0 + k] : 0.0f;
        }
        #pragma unroll
        for (int i = 0; i < 4; i++) {
            int idx = tid + 256 * i;
            int k = idx >> 6, n = idx & 63;
            Bs[k][n] = B[(size_t)(k0 + k) * N + bn + n];
        }
        __syncthreads();
        #pragma unroll
        for (int k = 0; k < 16; k++) {
            float a[4], b[4];
            #pragma unroll
            for (int i = 0; i < 4; i++) a[i] = As[k][ty + 16 * i];
            #pragma unroll
            for (int j = 0; j < 4; j++) b[j] = Bs[k][tx + 16 * j];
            #pragma unroll
            for (int i = 0; i < 4; i++)
                #pragma unroll
                for (int j = 0; j < 4; j++)
                    acc[i][j] = fmaf(a[i], b[j], acc[i][j]);
        }
        __syncthreads();
    }
    #pragma unroll
    for (int i = 0; i < 4; i++) {
        int m = bm + ty + 16 * i;
        if (m >= M) continue;
        #pragma unroll
        for (int j = 0; j < 4; j++) {
            int n = bn + tx + 16 * j;
            float v = acc[i][j] + bias[n];
            if (DO_SILU) v = v / (1.0f + expf(-v));
            C[(size_t)m * N + n] = v;
        }
    }
}

// ---------------------------------------------------------------------------
// Node-parallel fused kernel. One block per node.
// 576 threads; thread t owns filter column t (weights in registers).
// Chunked metadata prefetch (1 barrier / 32 edges) + 8-edge batches with
// double-buffered gates (1 barrier / batch). Register accumulators,
// single output write per node.
// ---------------------------------------------------------------------------
__device__ __forceinline__ int irrep_of(int k) {
    if (k < 128) return k;
    if (k < 320) return 128 + (k - 128) / 3;
    return 192 + (k - 320) / 5;
}

__global__ __launch_bounds__(576, 1) void node_kernel(
    const float* __restrict__ rbf, const float* __restrict__ fcut,
    const float* __restrict__ rsh, const int* __restrict__ edge_index,
    const float* __restrict__ Wrbf, const float* __restrict__ brbf,
    const float* __restrict__ x_sph,
    float* __restrict__ out_scalar, float* __restrict__ out_sph) {
    const float* __restrict__ scalar_out = g_scalar_out;

    __shared__ float rbf_s[MAXD_][24];      // padded rows: 96B -> float4-aligned
    __shared__ int   eid_s[MAXD_];
    __shared__ int   src_s[MAXD_];
    __shared__ float fc_s[MAXD_];
    __shared__ float gate_s[2][EPB_][2 * NUM_IRREPS_];

    const int t = threadIdx.x;
    const int n = blockIdx.x;

    const int off = g_offs[n];
    const int deg = g_count[n];
    if (deg == 0) return;

    // thread-owned filter column t
    float w[NUM_BASIS_];
    #pragma unroll
    for (int k = 0; k < NUM_BASIS_; k++) w[k] = Wrbf[k * HIDDEN_ + t];
    const float bb = brbf[t];
    const int ir = (t < SPH_DIM_) ? irrep_of(t) : 0;

    float acc_sph = 0.0f;     // t < 480
    float acc_sc  = 0.0f;     // t >= 448

    int pp = 0;               // gate buffer parity, continuous across chunks
    for (int c0 = 0; c0 < deg; c0 += MAXD_) {
        const int cnt = min(MAXD_, deg - c0);

        // ---- metadata prefetch for the whole chunk (pad with edge 0, fc=0)
        if (t < MAXD_) {
            int j = (t < cnt) ? t : 0;
            int eid = __ldg(&g_perm[off + c0 + j]);
            eid_s[t] = eid;
            src_s[t] = __ldg(&edge_index[N_EDGES_ + eid]);
            fc_s[t]  = (t < cnt) ? __ldg(&fcut[eid]) : 0.0f;
        }
        for (int i = t; i < MAXD_ * NUM_BASIS_; i += 576) {
            int e = i / NUM_BASIS_, k = i % NUM_BASIS_;
            int j = (e < cnt) ? e : 0;
            int eid = __ldg(&g_perm[off + c0 + j]);   // redundant, L1 broadcast
            rbf_s[e][k] = __ldg(&rbf[(size_t)eid * NUM_BASIS_ + k]);
        }
        __syncthreads();

        const int nb = (cnt + EPB_ - 1) / EPB_;
        for (int b = 0; b < nb; b++) {
            const int base = b * EPB_;

            // copy meta to regs (message phase must not touch meta smem)
            int srcv[EPB_], eidv[EPB_];
            float fcv[EPB_];
            #pragma unroll
            for (int e = 0; e < EPB_; e++) {
                srcv[e] = src_s[base + e];
                eidv[e] = eid_s[base + e];
                fcv[e]  = fc_s[base + e];
            }

            // gathers first (8-deep MLP)
            float s[EPB_];
            #pragma unroll
            for (int e = 0; e < EPB_; e++)
                s[e] = __ldg(&scalar_out[(size_t)srcv[e] * HIDDEN_ + t]);

            // filter dots: rbf via float4 broadcast LDS
            float a[EPB_];
            #pragma unroll
            for (int e = 0; e < EPB_; e++) {
                const float4* rp = reinterpret_cast<const float4*>(&rbf_s[base + e][0]);
                float4 q0 = rp[0], q1 = rp[1], q2 = rp[2], q3 = rp[3], q4 = rp[4];
                float v = bb;
                v = fmaf(q0.x, w[0],  v); v = fmaf(q0.y, w[1],  v);
                v = fmaf(q0.z, w[2],  v); v = fmaf(q0.w, w[3],  v);
                v = fmaf(q1.x, w[4],  v); v = fmaf(q1.y, w[5],  v);
                v = fmaf(q1.z, w[6],  v); v = fmaf(q1.w, w[7],  v);
                v = fmaf(q2.x, w[8],  v); v = fmaf(q2.y, w[9],  v);
                v = fmaf(q2.z, w[10], v); v = fmaf(q2.w, w[11], v);
                v = fmaf(q3.x, w[12], v); v = fmaf(q3.y, w[13], v);
                v = fmaf(q3.z, w[14], v); v = fmaf(q3.w, w[15], v);
                v = fmaf(q4.x, w[16], v); v = fmaf(q4.y, w[17], v);
                v = fmaf(q4.z, w[18], v); v = fmaf(q4.w, w[19], v);
                a[e] = v;
            }

            // fo = scalar_out[src] * filter_weight
            #pragma unroll
            for (int e = 0; e < EPB_; e++) s[e] = s[e] * (a[e] * fcv[e]);

            if (t < 2 * NUM_IRREPS_) {
                #pragma unroll
                for (int e = 0; e < EPB_; e++) gate_s[pp][e][t] = s[e];
            } else {
                #pragma unroll
                for (int e = 0; e < EPB_; e++) acc_sc += s[e];
            }
            __syncthreads();   // gates ready (also: prev reads of this buffer done)

            // ---- message phase ----
            if (t < SPH_DIM_) {
                #pragma unroll
                for (int e = 0; e < EPB_; e++) {
                    float xv = __ldg(&x_sph[(size_t)srcv[e] * SPH_DIM_ + t]);
                    float rv = __ldcs(&rsh[(size_t)eidv[e] * SPH_DIM_ + t]);
                    acc_sph = fmaf(xv, gate_s[pp][e][ir], acc_sph);
                    acc_sph = fmaf(rv, gate_s[pp][e][NUM_IRREPS_ + ir], acc_sph);
                }
            }
            pp ^= 1;
        }
    }

    // single write per node (out already holds residual)
    if (t < SPH_DIM_)
        out_sph[(size_t)n * SPH_DIM_ + t] += acc_sph;
    if (t >= 2 * NUM_IRREPS_)
        out_scalar[(size_t)n * NODE_DIM_ + (t - 2 * NUM_IRREPS_)] += acc_sc;
}

// ---------------------------------------------------------------------------
extern "C" void kernel_launch(void* const* d_in, const int* in_sizes, int n_in,
                              void* d_out, int out_size) {
    const float* x_scalar = (const float*)d_in[0];
    const float* x_sph    = (const float*)d_in[1];
    const float* rbf      = (const float*)d_in[2];
    const float* fcut     = (const float*)d_in[3];
    const float* rsh      = (const float*)d_in[4];
    const int*   eidx     = (const int*)d_in[5];
    const float* W1       = (const float*)d_in[6];
    const float* b1       = (const float*)d_in[7];
    const float* W2       = (const float*)d_in[8];
    const float* b2       = (const float*)d_in[9];
    const float* Wrbf     = (const float*)d_in[10];
    const float* brbf     = (const float*)d_in[11];

    float* out        = (float*)d_out;
    float* out_scalar = out;
    float* out_sph    = out + (size_t)N_NODES_ * NODE_DIM_;

    float* hidden = nullptr;
    float* so     = nullptr;
    cudaGetSymbolAddress((void**)&hidden, g_hidden);
    cudaGetSymbolAddress((void**)&so, g_scalar_out);

    // launch order puts the big GEMM at capture index 3 for profiling
    {
        int total4 = (N_NODES_ * NODE_DIM_ + N_NODES_ * SPH_DIM_) / 4;
        init_out_kernel<<<(total4 + 255) / 256, 256>>>(
            (const float4*)x_scalar, (const float4*)x_sph, (float4*)out);   // 0
    }
    hist_kernel<<<(N_EDGES_ + 255) / 256, 256>>>(eidx);                      // 1
    {
        dim3 grid(NODE_DIM_ / 64, (N_NODES_ + 63) / 64);
        sgemm_bias<true><<<grid, 256>>>(x_scalar, W1, b1, hidden,
                                        N_NODES_, NODE_DIM_, NODE_DIM_);     // 2
    }
    {
        dim3 grid(HIDDEN_ / 64, (N_NODES_ + 63) / 64);
        sgemm_bias<false><<<grid, 256>>>(hidden, W2, b2, so,
                                         N_NODES_, HIDDEN_, NODE_DIM_);      // 3
    }
    scan1_kernel<<<SCAN_BLKS_, 256>>>();                                     // 4
    scan2_kernel<<<1, 128>>>();                                              // 5
    scan3_kernel<<<SCAN_BLKS_, 256>>>();                                     // 6
    perm_kernel<<<(N_EDGES_ + 255) / 256, 256>>>(eidx);                      // 7

    node_kernel<<<N_NODES_, 576>>>(rbf, fcut, rsh, eidx, Wrbf, brbf,
                                   x_sph, out_scalar, out_sph);              // 8
}

// round 6
// speedup vs baseline: 1.8901x; 1.2525x over previous
#include <cuda_runtime.h>
#include <cstdint>
#include <math.h>

#define NODE_DIM_   128
#define NUM_IRREPS_ 224
#define SPH_DIM_    480
#define HIDDEN_     576
#define NUM_BASIS_  20
#define N_NODES_    30000
#define N_EDGES_    480000
#define EPB_        8
#define MAXD_       32
#define SCAN_BLKS_  118          // ceil(30000/256)

// Scratch (device globals)
__device__ float g_hidden[(size_t)N_NODES_ * NODE_DIM_];
__device__ float g_scalar_out[(size_t)N_NODES_ * HIDDEN_];
__device__ int   g_count[N_NODES_];
__device__ int   g_offs[N_NODES_];     // block-local exclusive (scan1)
__device__ int   g_cursor[N_NODES_];   // mutable copy for perm
__device__ int   g_part[128];          // per-scan-block totals -> exclusive
__device__ int   g_perm[N_EDGES_];

// ---------------- counting sort by dst ----------------
__global__ void zero_kernel() {
    int i = blockIdx.x * blockDim.x + threadIdx.x;
    if (i < N_NODES_) g_count[i] = 0;
}
__global__ void hist_kernel(const int* __restrict__ edge_index) {
    int e = blockIdx.x * blockDim.x + threadIdx.x;
    if (e < N_EDGES_) atomicAdd(&g_count[edge_index[e]], 1);   // dst = row 0
}
__global__ void scan1_kernel() {
    __shared__ int s[256];
    int tid = threadIdx.x;
    int i = blockIdx.x * 256 + tid;
    int v = (i < N_NODES_) ? g_count[i] : 0;
    s[tid] = v; __syncthreads();
    #pragma unroll
    for (int d = 1; d < 256; d <<= 1) {
        int x = (tid >= d) ? s[tid - d] : 0;
        __syncthreads();
        s[tid] += x;
        __syncthreads();
    }
    if (i < N_NODES_) {
        int o = s[tid] - v;          // exclusive within block
        g_offs[i] = o;
        g_cursor[i] = o;
    }
    if (tid == 255) g_part[blockIdx.x] = s[255];
}
__global__ void scan2_kernel() {
    __shared__ int s[128];
    int tid = threadIdx.x;
    int v = (tid < SCAN_BLKS_) ? g_part[tid] : 0;
    s[tid] = v; __syncthreads();
    #pragma unroll
    for (int d = 1; d < 128; d <<= 1) {
        int x = (tid >= d) ? s[tid - d] : 0;
        __syncthreads();
        s[tid] += x;
        __syncthreads();
    }
    if (tid < SCAN_BLKS_) g_part[tid] = s[tid] - v;    // exclusive
}
// perm with scan3 folded in: global offset = local cursor + part[block]
__global__ void perm_kernel(const int* __restrict__ edge_index) {
    int e = blockIdx.x * blockDim.x + threadIdx.x;
    if (e < N_EDGES_) {
        int d = edge_index[e];
        int p = atomicAdd(&g_cursor[d], 1) + g_part[d >> 8];
        g_perm[p] = e;
    }
}

// ---------------------------------------------------------------------------
// SGEMM 64x64, 4x4 microtile; B read as LDS.128 (contiguous n-tile tx*4+j)
// ---------------------------------------------------------------------------
template <bool DO_SILU>
__global__ __launch_bounds__(256) void sgemm_bias(
    const float* __restrict__ A, const float* __restrict__ B,
    const float* __restrict__ bias, float* __restrict__ C,
    int M, int N, int K) {
    __shared__ float As[16][65];
    __shared__ __align__(16) float Bs[16][64];
    const int bm = blockIdx.y * 64;
    const int bn = blockIdx.x * 64;
    const int tid = threadIdx.x;
    const int tx = tid & 15;
    const int ty = tid >> 4;
    float acc[4][4] = {};
    for (int k0 = 0; k0 < K; k0 += 16) {
        #pragma unroll
        for (int i = 0; i < 4; i++) {
            int idx = tid + 256 * i;
            int m = idx >> 4, k = idx & 15;
            int gm = bm + m;
            As[k][m] = (gm < M) ? A[(size_t)gm * K + k0 + k] : 0.0f;
        }
        #pragma unroll
        for (int i = 0; i < 4; i++) {
            int idx = tid + 256 * i;
            int k = idx >> 6, n = idx & 63;
            Bs[k][n] = B[(size_t)(k0 + k) * N + bn + n];
        }
        __syncthreads();
        #pragma unroll
        for (int k = 0; k < 16; k++) {
            float a[4];
            #pragma unroll
            for (int i = 0; i < 4; i++) a[i] = As[k][ty + 16 * i];
            float4 bq = *reinterpret_cast<const float4*>(&Bs[k][tx * 4]);
            float b[4] = {bq.x, bq.y, bq.z, bq.w};
            #pragma unroll
            for (int i = 0; i < 4; i++)
                #pragma unroll
                for (int j = 0; j < 4; j++)
                    acc[i][j] = fmaf(a[i], b[j], acc[i][j]);
        }
        __syncthreads();
    }
    #pragma unroll
    for (int i = 0; i < 4; i++) {
        int m = bm + ty + 16 * i;
        if (m >= M) continue;
        #pragma unroll
        for (int j = 0; j < 4; j++) {
            int n = bn + tx * 4 + j;
            float v = acc[i][j] + bias[n];
            if (DO_SILU) v = v / (1.0f + expf(-v));
            C[(size_t)m * N + n] = v;
        }
    }
}

// ---------------------------------------------------------------------------
// Persistent node-parallel fused kernel. grid=148, 576 threads.
// Thread t owns filter column t; weights resident in registers for all nodes.
// Per 8-edge batch: all gathers issued BEFORE the single barrier.
// Writes out = residual + accumulator (handles deg=0 too; no init kernel).
// ---------------------------------------------------------------------------
__device__ __forceinline__ int irrep_of(int k) {
    if (k < 128) return k;
    if (k < 320) return 128 + (k - 128) / 3;
    return 192 + (k - 320) / 5;
}

__global__ __launch_bounds__(576, 1) void node_kernel(
    const float* __restrict__ rbf, const float* __restrict__ fcut,
    const float* __restrict__ rsh, const int* __restrict__ edge_index,
    const float* __restrict__ Wrbf, const float* __restrict__ brbf,
    const float* __restrict__ x_scalar, const float* __restrict__ x_sph,
    float* __restrict__ out_scalar, float* __restrict__ out_sph) {
    const float* __restrict__ scalar_out = g_scalar_out;

    __shared__ __align__(16) float rbf_s[MAXD_][24];
    __shared__ int   eid_s[MAXD_];
    __shared__ int   src_s[MAXD_];
    __shared__ float fc_s[MAXD_];
    __shared__ float gate_s[2][EPB_][2 * NUM_IRREPS_];

    const int t = threadIdx.x;

    // resident filter column t
    float w[NUM_BASIS_];
    #pragma unroll
    for (int k = 0; k < NUM_BASIS_; k++) w[k] = Wrbf[k * HIDDEN_ + t];
    const float bb = brbf[t];
    const int ir = (t < SPH_DIM_) ? irrep_of(t) : 0;

    int pp = 0;   // gate buffer parity (continuous; safe across nodes/chunks)

    for (int n = blockIdx.x; n < N_NODES_; n += gridDim.x) {
        const int off = g_offs[n] + g_part[n >> 8];
        const int deg = g_count[n];

        float acc_sph = 0.0f;     // t < 480
        float acc_sc  = 0.0f;     // t >= 448

        for (int c0 = 0; c0 < deg; c0 += MAXD_) {
            const int cnt = min(MAXD_, deg - c0);

            // ---- chunk metadata prefetch (pad with edge j=0, fc=0) ----
            if (t < MAXD_) {
                int j = (t < cnt) ? t : 0;
                int eid = __ldg(&g_perm[off + c0 + j]);
                eid_s[t] = eid;
                src_s[t] = __ldg(&edge_index[N_EDGES_ + eid]);
                fc_s[t]  = (t < cnt) ? __ldg(&fcut[eid]) : 0.0f;
            }
            for (int i = t; i < MAXD_ * NUM_BASIS_; i += 576) {
                int e = i / NUM_BASIS_, k = i % NUM_BASIS_;
                int j = (e < cnt) ? e : 0;
                int eid = __ldg(&g_perm[off + c0 + j]);   // L1 broadcast
                rbf_s[e][k] = __ldg(&rbf[(size_t)eid * NUM_BASIS_ + k]);
            }
            __syncthreads();

            const int nb = (cnt + EPB_ - 1) / EPB_;
            for (int b = 0; b < nb; b++) {
                const int base = b * EPB_;

                int srcv[EPB_], eidv[EPB_];
                float fcv[EPB_];
                #pragma unroll
                for (int e = 0; e < EPB_; e++) {
                    srcv[e] = src_s[base + e];
                    eidv[e] = eid_s[base + e];
                    fcv[e]  = fc_s[base + e];
                }

                // all gathers issued up front (coalesced: warp = 32 consec t)
                float s[EPB_];
                #pragma unroll
                for (int e = 0; e < EPB_; e++)
                    s[e] = __ldg(&scalar_out[(size_t)srcv[e] * HIDDEN_ + t]);

                float xv[EPB_], rv[EPB_];
                if (t < SPH_DIM_) {
                    #pragma unroll
                    for (int e = 0; e < EPB_; e++) {
                        xv[e] = __ldg(&x_sph[(size_t)srcv[e] * SPH_DIM_ + t]);
                        rv[e] = __ldcs(&rsh[(size_t)eidv[e] * SPH_DIM_ + t]);
                    }
                }

                // filter dots: rbf via float4 broadcast LDS (overlaps gathers)
                float a[EPB_];
                #pragma unroll
                for (int e = 0; e < EPB_; e++) {
                    const float4* rp =
                        reinterpret_cast<const float4*>(&rbf_s[base + e][0]);
                    float4 q0 = rp[0], q1 = rp[1], q2 = rp[2], q3 = rp[3], q4 = rp[4];
                    float v = bb;
                    v = fmaf(q0.x, w[0],  v); v = fmaf(q0.y, w[1],  v);
                    v = fmaf(q0.z, w[2],  v); v = fmaf(q0.w, w[3],  v);
                    v = fmaf(q1.x, w[4],  v); v = fmaf(q1.y, w[5],  v);
                    v = fmaf(q1.z, w[6],  v); v = fmaf(q1.w, w[7],  v);
                    v = fmaf(q2.x, w[8],  v); v = fmaf(q2.y, w[9],  v);
                    v = fmaf(q2.z, w[10], v); v = fmaf(q2.w, w[11], v);
                    v = fmaf(q3.x, w[12], v); v = fmaf(q3.y, w[13], v);
                    v = fmaf(q3.z, w[14], v); v = fmaf(q3.w, w[15], v);
                    v = fmaf(q4.x, w[16], v); v = fmaf(q4.y, w[17], v);
                    v = fmaf(q4.z, w[18], v); v = fmaf(q4.w, w[19], v);
                    a[e] = v;
                }

                #pragma unroll
                for (int e = 0; e < EPB_; e++) s[e] = s[e] * (a[e] * fcv[e]);

                if (t < 2 * NUM_IRREPS_) {
                    #pragma unroll
                    for (int e = 0; e < EPB_; e++) gate_s[pp][e][t] = s[e];
                } else {
                    #pragma unroll
                    for (int e = 0; e < EPB_; e++) acc_sc += s[e];
                }
                __syncthreads();   // gates ready; gathers land during wait

                if (t < SPH_DIM_) {
                    #pragma unroll
                    for (int e = 0; e < EPB_; e++) {
                        acc_sph = fmaf(xv[e], gate_s[pp][e][ir], acc_sph);
                        acc_sph = fmaf(rv[e], gate_s[pp][e][NUM_IRREPS_ + ir],
                                       acc_sph);
                    }
                }
                pp ^= 1;
            }
        }

        // residual + single write (covers deg==0 nodes too)
        if (t < SPH_DIM_)
            out_sph[(size_t)n * SPH_DIM_ + t] =
                x_sph[(size_t)n * SPH_DIM_ + t] + acc_sph;
        if (t >= 2 * NUM_IRREPS_) {
            int c = t - 2 * NUM_IRREPS_;
            out_scalar[(size_t)n * NODE_DIM_ + c] =
                x_scalar[(size_t)n * NODE_DIM_ + c] + acc_sc;
        }
    }
}

// ---------------------------------------------------------------------------
extern "C" void kernel_launch(void* const* d_in, const int* in_sizes, int n_in,
                              void* d_out, int out_size) {
    const float* x_scalar = (const float*)d_in[0];
    const float* x_sph    = (const float*)d_in[1];
    const float* rbf      = (const float*)d_in[2];
    const float* fcut     = (const float*)d_in[3];
    const float* rsh      = (const float*)d_in[4];
    const int*   eidx     = (const int*)d_in[5];
    const float* W1       = (const float*)d_in[6];
    const float* b1       = (const float*)d_in[7];
    const float* W2       = (const float*)d_in[8];
    const float* b2       = (const float*)d_in[9];
    const float* Wrbf     = (const float*)d_in[10];
    const float* brbf     = (const float*)d_in[11];

    float* out        = (float*)d_out;
    float* out_scalar = out;
    float* out_sph    = out + (size_t)N_NODES_ * NODE_DIM_;

    float* hidden = nullptr;
    float* so     = nullptr;
    cudaGetSymbolAddress((void**)&hidden, g_hidden);
    cudaGetSymbolAddress((void**)&so, g_scalar_out);

    zero_kernel<<<SCAN_BLKS_, 256>>>();                                      // 0
    hist_kernel<<<(N_EDGES_ + 255) / 256, 256>>>(eidx);                      // 1
    {
        dim3 grid(NODE_DIM_ / 64, (N_NODES_ + 63) / 64);
        sgemm_bias<true><<<grid, 256>>>(x_scalar, W1, b1, hidden,
                                        N_NODES_, NODE_DIM_, NODE_DIM_);     // 2
    }
    {
        dim3 grid(HIDDEN_ / 64, (N_NODES_ + 63) / 64);
        sgemm_bias<false><<<grid, 256>>>(hidden, W2, b2, so,
                                         N_NODES_, HIDDEN_, NODE_DIM_);      // 3
    }
    scan1_kernel<<<SCAN_BLKS_, 256>>>();                                     // 4
    scan2_kernel<<<1, 128>>>();                                              // 5
    perm_kernel<<<(N_EDGES_ + 255) / 256, 256>>>(eidx);                      // 6

    node_kernel<<<148, 576>>>(rbf, fcut, rsh, eidx, Wrbf, brbf,
                              x_scalar, x_sph, out_scalar, out_sph);         // 7
}